// round 1
// baseline (speedup 1.0000x reference)
#include <cuda_runtime.h>

#define N_NODES_MAX 100000
#define HIDDEN 64

// Scratch (no allocations allowed in kernel_launch)
__device__ float g_dinv[N_NODES_MAX];    // holds deg, then dinv (in place)
__device__ float g_accum[N_NODES_MAX];   // edge scatter accumulator
__device__ float g_px[N_NODES_MAX];      // dinv[i]*x[i] (pre-scaled source values)
__device__ float g_uz[HIDDEN], g_cz[HIDDEN], g_uh[HIDDEN], g_ch[HIDDEN];

// --- init: deg starts at 1.0 (self-loop weight), accum at 0 ---
__global__ void init_kernel(int n) {
    int i = blockIdx.x * blockDim.x + threadIdx.x;
    if (i < n) { g_dinv[i] = 1.0f; g_accum[i] = 0.0f; }
}

// --- fold the tiny matrices: uz = Wz @ Lz_top, cz = bz @ Lz_top + lbz, etc. ---
__global__ void const_kernel(const float* __restrict__ Wz, const float* __restrict__ bz,
                             const float* __restrict__ Lz, const float* __restrict__ lbz,
                             const float* __restrict__ Wh, const float* __restrict__ bh,
                             const float* __restrict__ Lh, const float* __restrict__ lbh) {
    int j = threadIdx.x;
    if (j < HIDDEN) {
        float uz = 0.f, cz = lbz[j], uh = 0.f, ch = lbh[j];
        #pragma unroll 8
        for (int k = 0; k < HIDDEN; k++) {
            float lz = Lz[k * HIDDEN + j];
            float lh = Lh[k * HIDDEN + j];
            uz += Wz[k] * lz;
            cz += bz[k] * lz;
            uh += Wh[k] * lh;
            ch += bh[k] * lh;
        }
        g_uz[j] = uz; g_cz[j] = cz; g_uh[j] = uh; g_ch[j] = ch;
    }
}

// --- pass 1 over edges: degree accumulation ---
__global__ void deg_kernel(const int* __restrict__ dst, const float* __restrict__ ew, int E) {
    int e = blockIdx.x * blockDim.x + threadIdx.x;
    if (e < E) atomicAdd(&g_dinv[dst[e]], ew[e]);
}

// --- dinv + pre-scale x ---
__global__ void dinv_kernel(const float* __restrict__ x, int n) {
    int i = blockIdx.x * blockDim.x + threadIdx.x;
    if (i < n) {
        float d  = g_dinv[i];
        float di = (d > 0.f) ? rsqrtf(d) : 0.f;
        g_dinv[i] = di;
        g_px[i]   = di * x[i];
    }
}

// --- pass 2 over edges: normalized scatter-add ---
__global__ void agg_kernel(const int* __restrict__ src, const int* __restrict__ dst,
                           const float* __restrict__ ew, int E) {
    int e = blockIdx.x * blockDim.x + threadIdx.x;
    if (e < E) atomicAdd(&g_accum[dst[e]], ew[e] * g_px[src[e]]);
}

// --- pointwise epilogue: whole TGCN cell collapses to f(a[i]) ---
__global__ void out_kernel(const float* __restrict__ x, const float* __restrict__ Wout,
                           const float* __restrict__ bout, float* __restrict__ out, int n) {
    __shared__ float s_uz[HIDDEN], s_cz[HIDDEN], s_uh[HIDDEN], s_ch[HIDDEN], s_w[HIDDEN];
    for (int j = threadIdx.x; j < HIDDEN; j += blockDim.x) {
        s_uz[j] = g_uz[j]; s_cz[j] = g_cz[j];
        s_uh[j] = g_uh[j]; s_ch[j] = g_ch[j];
        s_w[j]  = Wout[j];
    }
    __syncthreads();
    int i = blockIdx.x * blockDim.x + threadIdx.x;
    if (i < n) {
        float di = g_dinv[i];
        float a  = di * (g_accum[i] + di * x[i]);
        float acc = bout[0];
        #pragma unroll 8
        for (int j = 0; j < HIDDEN; j++) {
            // z = sigmoid(a*uz + cz)
            float zarg = fmaf(a, s_uz[j], s_cz[j]);
            float z = __fdividef(1.0f, 1.0f + __expf(-zarg));
            // ht = tanh(a*uh + ch) via exp, clamped for robustness
            float targ = fmaf(a, s_uh[j], s_ch[j]);
            targ = fminf(fmaxf(targ, -15.0f), 15.0f);
            float t2 = __expf(2.0f * targ);
            float th = __fdividef(t2 - 1.0f, t2 + 1.0f);
            // Hn = (1-z)*ht  (H0 = 0, so Z*H term vanishes; R branch dead)
            float h = fmaxf((1.0f - z) * th, 0.0f);
            acc = fmaf(h, s_w[j], acc);
        }
        out[i] = acc;
    }
}

extern "C" void kernel_launch(void* const* d_in, const int* in_sizes, int n_in,
                              void* d_out, int out_size) {
    const float* x    = (const float*)d_in[0];
    const float* ew   = (const float*)d_in[1];
    const float* Wz   = (const float*)d_in[2];
    const float* bz   = (const float*)d_in[3];
    const float* Lz   = (const float*)d_in[4];
    const float* lbz  = (const float*)d_in[5];
    // d_in[6..9]: Wr, br, Lr, lbr -- dead (H0 = 0 makes H*R = 0)
    const float* Wh   = (const float*)d_in[10];
    const float* bh   = (const float*)d_in[11];
    const float* Lh   = (const float*)d_in[12];
    const float* lbh  = (const float*)d_in[13];
    const float* Wout = (const float*)d_in[14];
    const float* bout = (const float*)d_in[15];
    const int*   eidx = (const int*)d_in[16];

    int N = in_sizes[0];           // x is [N,1]
    int E = in_sizes[1];           // edge_weight count
    const int* src = eidx;         // edge_index row 0
    const int* dst = eidx + E;     // edge_index row 1

    float* out = (float*)d_out;

    const int TB = 256;
    int nb_n = (N + TB - 1) / TB;
    int nb_e = (E + TB - 1) / TB;

    init_kernel<<<nb_n, TB>>>(N);
    const_kernel<<<1, HIDDEN>>>(Wz, bz, Lz, lbz, Wh, bh, Lh, lbh);
    deg_kernel<<<nb_e, TB>>>(dst, ew, E);
    dinv_kernel<<<nb_n, TB>>>(x, N);
    agg_kernel<<<nb_e, TB>>>(src, dst, ew, E);
    out_kernel<<<nb_n, TB>>>(x, Wout, bout, out, N);
}

// round 2
// speedup vs baseline: 1.1222x; 1.1222x over previous
#include <cuda_runtime.h>
#include <cstdint>

#define N_NODES_MAX 100000
#define HIDDEN 64

// Scratch. INVARIANT: g_deg and g_accum are all-zero between kernel_launch
// calls (static zero-init establishes it; dinv_kernel / out_kernel restore it).
__device__ float g_deg[N_NODES_MAX];     // zero between calls
__device__ float g_dinv[N_NODES_MAX];
__device__ float g_accum[N_NODES_MAX];   // zero between calls
__device__ float g_px[N_NODES_MAX];      // dinv[i]*x[i]
__device__ float g_uz[HIDDEN], g_cz[HIDDEN], g_uh[HIDDEN], g_ch[HIDDEN];

__device__ __forceinline__ float tanh_approx(float x) {
    float y;
    asm("tanh.approx.f32 %0, %1;" : "=f"(y) : "f"(x));
    return y;
}

// --- pass 1 over edges: degree accumulation (+ const fold in block 0) ---
__global__ void deg_kernel(const int* __restrict__ dst, const float* __restrict__ ew,
                           int E, int vec_ok,
                           const float* __restrict__ Wz, const float* __restrict__ bz,
                           const float* __restrict__ Lz, const float* __restrict__ lbz,
                           const float* __restrict__ Wh, const float* __restrict__ bh,
                           const float* __restrict__ Lh, const float* __restrict__ lbh) {
    // fold tiny matrices once: uz = Wz@Lz_top, cz = bz@Lz_top + lbz, same for h
    if (blockIdx.x == 0 && threadIdx.x < HIDDEN) {
        int j = threadIdx.x;
        float uz = 0.f, cz = lbz[j], uh = 0.f, ch = lbh[j];
        #pragma unroll 8
        for (int k = 0; k < HIDDEN; k++) {
            float lz = Lz[k * HIDDEN + j];
            float lh = Lh[k * HIDDEN + j];
            uz = fmaf(Wz[k], lz, uz);
            cz = fmaf(bz[k], lz, cz);
            uh = fmaf(Wh[k], lh, uh);
            ch = fmaf(bh[k], lh, ch);
        }
        g_uz[j] = uz; g_cz[j] = cz; g_uh[j] = uh; g_ch[j] = ch;
    }

    int tid = blockIdx.x * blockDim.x + threadIdx.x;
    if (vec_ok) {
        int nvec = E >> 2;
        if (tid < nvec) {
            int4   d4 = ((const int4*)dst)[tid];
            float4 w4 = ((const float4*)ew)[tid];
            atomicAdd(&g_deg[d4.x], w4.x);
            atomicAdd(&g_deg[d4.y], w4.y);
            atomicAdd(&g_deg[d4.z], w4.z);
            atomicAdd(&g_deg[d4.w], w4.w);
        }
        // tail
        int e = (nvec << 2) + tid;
        if (e < E && tid < (E - (nvec << 2)))
            atomicAdd(&g_deg[dst[e]], ew[e]);
    } else {
        for (int e = tid; e < E; e += gridDim.x * blockDim.x)
            atomicAdd(&g_deg[dst[e]], ew[e]);
    }
}

// --- dinv + pre-scale x; resets g_deg to keep the zero invariant ---
__global__ void dinv_kernel(const float* __restrict__ x, int n) {
    int i = blockIdx.x * blockDim.x + threadIdx.x;
    if (i < n) {
        float d  = g_deg[i] + 1.0f;     // +1 self-loop weight
        g_deg[i] = 0.0f;                // restore invariant for next call
        float di = rsqrtf(d);           // d >= 1 always
        g_dinv[i] = di;
        g_px[i]   = di * x[i];
    }
}

// --- pass 2 over edges: normalized scatter-add ---
__global__ void agg_kernel(const int* __restrict__ src, const int* __restrict__ dst,
                           const float* __restrict__ ew, int E, int vec_ok) {
    int tid = blockIdx.x * blockDim.x + threadIdx.x;
    if (vec_ok) {
        int nvec = E >> 2;
        if (tid < nvec) {
            int4   s4 = ((const int4*)src)[tid];
            int4   d4 = ((const int4*)dst)[tid];
            float4 w4 = ((const float4*)ew)[tid];
            float p0 = __ldg(&g_px[s4.x]);
            float p1 = __ldg(&g_px[s4.y]);
            float p2 = __ldg(&g_px[s4.z]);
            float p3 = __ldg(&g_px[s4.w]);
            atomicAdd(&g_accum[d4.x], w4.x * p0);
            atomicAdd(&g_accum[d4.y], w4.y * p1);
            atomicAdd(&g_accum[d4.z], w4.z * p2);
            atomicAdd(&g_accum[d4.w], w4.w * p3);
        }
        int e = (nvec << 2) + tid;
        if (e < E && tid < (E - (nvec << 2)))
            atomicAdd(&g_accum[dst[e]], ew[e] * __ldg(&g_px[src[e]]));
    } else {
        for (int e = tid; e < E; e += gridDim.x * blockDim.x)
            atomicAdd(&g_accum[dst[e]], ew[e] * __ldg(&g_px[src[e]]));
    }
}

// --- pointwise epilogue; resets g_accum to keep the zero invariant ---
__global__ void out_kernel(const float* __restrict__ x, const float* __restrict__ Wout,
                           const float* __restrict__ bout, float* __restrict__ out, int n) {
    __shared__ float s_uz[HIDDEN], s_cz[HIDDEN], s_uh[HIDDEN], s_ch[HIDDEN], s_w[HIDDEN];
    for (int j = threadIdx.x; j < HIDDEN; j += blockDim.x) {
        s_uz[j] = g_uz[j]; s_cz[j] = g_cz[j];
        s_uh[j] = g_uh[j]; s_ch[j] = g_ch[j];
        s_w[j]  = Wout[j];
    }
    __syncthreads();
    int i = blockIdx.x * blockDim.x + threadIdx.x;
    if (i < n) {
        float di  = g_dinv[i];
        float acc0 = g_accum[i];
        g_accum[i] = 0.0f;              // restore invariant for next call
        float a   = di * (acc0 + di * x[i]);
        float acc = bout[0];
        #pragma unroll 8
        for (int j = 0; j < HIDDEN; j++) {
            // z = sigmoid(zarg) = 0.5*tanh(zarg/2) + 0.5  ->  (1-z) = 0.5*(1 - tz)
            float zarg = fmaf(a, s_uz[j], s_cz[j]);
            float tz = tanh_approx(0.5f * zarg);
            float th = tanh_approx(fmaf(a, s_uh[j], s_ch[j]));
            // Hn = (1-Z)*Ht   (H0=0 kills Z*H; R branch dead)
            float h = fmaxf(0.5f * (1.0f - tz) * th, 0.0f);
            acc = fmaf(h, s_w[j], acc);
        }
        out[i] = acc;
    }
}

extern "C" void kernel_launch(void* const* d_in, const int* in_sizes, int n_in,
                              void* d_out, int out_size) {
    const float* x    = (const float*)d_in[0];
    const float* ew   = (const float*)d_in[1];
    const float* Wz   = (const float*)d_in[2];
    const float* bz   = (const float*)d_in[3];
    const float* Lz   = (const float*)d_in[4];
    const float* lbz  = (const float*)d_in[5];
    // d_in[6..9]: Wr, br, Lr, lbr -- dead (H0 = 0 makes H*R = 0)
    const float* Wh   = (const float*)d_in[10];
    const float* bh   = (const float*)d_in[11];
    const float* Lh   = (const float*)d_in[12];
    const float* lbh  = (const float*)d_in[13];
    const float* Wout = (const float*)d_in[14];
    const float* bout = (const float*)d_in[15];
    const int*   eidx = (const int*)d_in[16];

    int N = in_sizes[0];           // x is [N,1]
    int E = in_sizes[1];           // edge_weight count
    const int* src = eidx;
    const int* dst = eidx + E;

    float* out = (float*)d_out;

    // vectorized path requires 16B alignment of all three edge arrays
    int vec_ok = (((uintptr_t)src & 15) == 0) && (((uintptr_t)dst & 15) == 0) &&
                 (((uintptr_t)ew  & 15) == 0);

    const int TB = 256;
    int nb_n = (N + TB - 1) / TB;
    int nb_e;
    if (vec_ok) {
        int nvec = E >> 2;
        nb_e = (nvec + TB - 1) / TB;
        if (nb_e < 1) nb_e = 1;
    } else {
        nb_e = (E + TB - 1) / TB;
    }

    deg_kernel<<<nb_e, TB>>>(dst, ew, E, vec_ok, Wz, bz, Lz, lbz, Wh, bh, Lh, lbh);
    dinv_kernel<<<nb_n, TB>>>(x, N);
    agg_kernel<<<nb_e, TB>>>(src, dst, ew, E, vec_ok);
    out_kernel<<<nb_n, TB>>>(x, Wout, bout, out, N);
}